// round 6
// baseline (speedup 1.0000x reference)
#include <cuda_runtime.h>
#include <cuda_bf16.h>

#define B_ 2
#define HW_ 8192
#define D_ 512
#define L_ 4096
#define KN_ 32
#define HEADS_ 8
#define DH_ 64
#define INNER_ 512
#define MQ (B_ * HW_)   /* 16384 */
#define MC (B_ * L_)    /* 8192  */

// ---------------- device-global scratch (no cudaMalloc allowed) -------------
__device__ float g_q[MQ * INNER_];            // fp32 q (attn consumes fp32)
__device__ float g_kv[MC * 2 * INNER_];       // fp32 kv (attn consumes fp32)
__device__ __nv_bfloat16 g_x_hi[MQ * D_],          g_x_lo[MQ * D_];
__device__ __nv_bfloat16 g_c_hi[MC * D_],          g_c_lo[MC * D_];
__device__ __nv_bfloat16 g_wq_hi[D_ * INNER_],     g_wq_lo[D_ * INNER_];
__device__ __nv_bfloat16 g_wkv_hi[D_ * 2 * INNER_], g_wkv_lo[D_ * 2 * INNER_];
__device__ __nv_bfloat16 g_wo_hi[INNER_ * D_],     g_wo_lo[INNER_ * D_];
__device__ __nv_bfloat16 g_at_hi[MQ * INNER_],     g_at_lo[MQ * INNER_];

// ---------------- helpers ----------------------------------------------------
__device__ __forceinline__ void split_pack(float a, float b,
                                           unsigned &whi, unsigned &wlo) {
    __nv_bfloat16 ah = __float2bfloat16(a);
    __nv_bfloat16 bh = __float2bfloat16(b);
    __nv_bfloat16 al = __float2bfloat16(a - __bfloat162float(ah));
    __nv_bfloat16 bl = __float2bfloat16(b - __bfloat162float(bh));
    unsigned short ahu = *(unsigned short*)&ah, bhu = *(unsigned short*)&bh;
    unsigned short alu = *(unsigned short*)&al, blu = *(unsigned short*)&bl;
    whi = ((unsigned)bhu << 16) | ahu;
    wlo = ((unsigned)blu << 16) | alu;
}

__device__ __forceinline__ void ldsm_x4(uint4 &r, unsigned addr) {
    asm volatile("ldmatrix.sync.aligned.m8n8.x4.shared.b16 {%0,%1,%2,%3}, [%4];"
        : "=r"(r.x), "=r"(r.y), "=r"(r.z), "=r"(r.w) : "r"(addr));
}
__device__ __forceinline__ void ldsm_x4_t(uint4 &r, unsigned addr) {
    asm volatile("ldmatrix.sync.aligned.m8n8.x4.trans.shared.b16 {%0,%1,%2,%3}, [%4];"
        : "=r"(r.x), "=r"(r.y), "=r"(r.z), "=r"(r.w) : "r"(addr));
}
__device__ __forceinline__ void mma_bf16(float4 &d, const uint4 &a,
                                         unsigned b0, unsigned b1) {
    asm volatile("mma.sync.aligned.m16n8k16.row.col.f32.bf16.bf16.f32 "
        "{%0,%1,%2,%3}, {%4,%5,%6,%7}, {%8,%9}, {%0,%1,%2,%3};"
        : "+f"(d.x), "+f"(d.y), "+f"(d.z), "+f"(d.w)
        : "r"(a.x), "r"(a.y), "r"(a.z), "r"(a.w), "r"(b0), "r"(b1));
}
__device__ __forceinline__ void cp16(unsigned saddr, const void* gaddr) {
    asm volatile("cp.async.cg.shared.global [%0], [%1], 16;"
        :: "r"(saddr), "l"(gaddr));
}

// ---------------- fp32 -> bf16 hi/lo split (memory-bound) -------------------
__global__ __launch_bounds__(256) void split_kernel(
    const float4* __restrict__ src, uint2* __restrict__ hi,
    uint2* __restrict__ lo, int n4)
{
    int i = blockIdx.x * 256 + threadIdx.x;
    if (i >= n4) return;
    float4 v = src[i];
    unsigned h0, l0, h1, l1;
    split_pack(v.x, v.y, h0, l0);
    split_pack(v.z, v.w, h1, l1);
    hi[i] = make_uint2(h0, h1);
    lo[i] = make_uint2(l0, l1);
}

// ---------------------------------------------------------------------------
// Tensor-core GEMM, bf16 hi/lo split inputs (pre-converted in global).
// C[M,N] = A[M,K] @ B[K,N] (+ bias). 128x128x32 tiles, 512 thr, 16 warps 4x4,
// warp tile 32x32. 3-stage cp.async pipeline, one __syncthreads per K-tile.
// Inner loop is PASS-MAJOR: 8 independent accumulators between reuses of any
// accumulator, covering HMMA acc->acc latency (R4 had chains of 3 dependent
// MMAs on the same accumulator -> tensor pipe 33.5%).
// ---------------------------------------------------------------------------
#define AW 20
#define BW 68
#define STG_W 9472            /* words per stage: 2*2560 (A) + 2*2176 (B) */
#define SMEM_BYTES (3 * STG_W * 4)

__global__ __launch_bounds__(512) void gemm_bf16s(
    const __nv_bfloat16* __restrict__ Ah, const __nv_bfloat16* __restrict__ Al,
    const __nv_bfloat16* __restrict__ Bh, const __nv_bfloat16* __restrict__ Bl,
    float* __restrict__ C, int M, int N, int K, const float* __restrict__ bias)
{
    extern __shared__ unsigned sm[];
    const unsigned smbase = (unsigned)__cvta_generic_to_shared(sm);

    const int tid  = threadIdx.x;
    const int lane = tid & 31;
    const int warp = tid >> 5;
    const int wm   = (warp >> 2) * 32;
    const int wn   = (warp & 3) * 32;
    const int blockRow = blockIdx.y * 128;
    const int blockCol = blockIdx.x * 128;

    // cp.async loader map: A 128 rows x 4 chunks, B 32 rows x 16 chunks
    const int ar = tid >> 2, ac = tid & 3;
    const int bk = tid >> 4, bc = tid & 15;
    const __nv_bfloat16* gAh = Ah + (size_t)(blockRow + ar) * K + ac * 8;
    const __nv_bfloat16* gAl = Al + (size_t)(blockRow + ar) * K + ac * 8;
    const __nv_bfloat16* gBh = Bh + (size_t)bk * N + blockCol + bc * 8;
    const __nv_bfloat16* gBl = Bl + (size_t)bk * N + blockCol + bc * 8;
    const unsigned a_sb = ar * 80 + ac * 16;    // byte offset in stage
    const unsigned b_sb = bk * 272 + bc * 16;

    // ldmatrix lane maps (word offsets)
    const int a_l_row = lane & 15;
    const int a_l_k   = (lane >> 4) << 2;
    const int b_l_k   = (lane & 7) + ((lane >> 4) << 3);
    const int b_l_n   = ((lane >> 3) & 1) << 2;

    float4 d[2][4];
    #pragma unroll
    for (int i = 0; i < 2; i++)
        #pragma unroll
        for (int j = 0; j < 4; j++) d[i][j] = make_float4(0.f, 0.f, 0.f, 0.f);

    auto issue = [&](int stage, int k0) {
        unsigned s = smbase + stage * (STG_W * 4);
        cp16(s + a_sb,               gAh + k0);
        cp16(s + 2560 * 4 + a_sb,    gAl + k0);
        cp16(s + 5120 * 4 + b_sb,    gBh + (size_t)k0 * N);
        cp16(s + 7296 * 4 + b_sb,    gBl + (size_t)k0 * N);
    };

    // prologue: stages 0,1 in flight
    issue(0, 0);
    asm volatile("cp.async.commit_group;" ::: "memory");
    issue(1, 32);
    asm volatile("cp.async.commit_group;" ::: "memory");
    asm volatile("cp.async.wait_group 1;" ::: "memory");
    __syncthreads();

    const int nK = K >> 5;
    for (int i = 0; i < nK; i++) {
        const int stage = i % 3;
        const int kn = (i + 2) << 5;
        if (kn < K) issue((i + 2) % 3, kn);
        asm volatile("cp.async.commit_group;" ::: "memory");

        const unsigned sb = smbase + stage * (STG_W * 4);
        #pragma unroll
        for (int kk = 0; kk < 2; kk++) {
            uint4 ah[2], al[2], bh[2], bl[2];
            #pragma unroll
            for (int im = 0; im < 2; im++) {
                unsigned w = ((wm + im * 16 + a_l_row) * AW + kk * 8 + a_l_k) * 4;
                ldsm_x4(ah[im], sb + w);
                ldsm_x4(al[im], sb + 2560 * 4 + w);
            }
            #pragma unroll
            for (int ib = 0; ib < 2; ib++) {
                unsigned w = ((kk * 16 + b_l_k) * BW + ((wn + ib * 16) >> 1) + b_l_n) * 4;
                ldsm_x4_t(bh[ib], sb + 5120 * 4 + w);
                ldsm_x4_t(bl[ib], sb + 7296 * 4 + w);
            }
            // pass 1: hi*hi — 8 independent accumulators
            #pragma unroll
            for (int im = 0; im < 2; im++)
                #pragma unroll
                for (int ib = 0; ib < 2; ib++) {
                    mma_bf16(d[im][ib * 2 + 0], ah[im], bh[ib].x, bh[ib].z);
                    mma_bf16(d[im][ib * 2 + 1], ah[im], bh[ib].y, bh[ib].w);
                }
            // pass 2: hi*lo
            #pragma unroll
            for (int im = 0; im < 2; im++)
                #pragma unroll
                for (int ib = 0; ib < 2; ib++) {
                    mma_bf16(d[im][ib * 2 + 0], ah[im], bl[ib].x, bl[ib].z);
                    mma_bf16(d[im][ib * 2 + 1], ah[im], bl[ib].y, bl[ib].w);
                }
            // pass 3: lo*hi
            #pragma unroll
            for (int im = 0; im < 2; im++)
                #pragma unroll
                for (int ib = 0; ib < 2; ib++) {
                    mma_bf16(d[im][ib * 2 + 0], al[im], bh[ib].x, bh[ib].z);
                    mma_bf16(d[im][ib * 2 + 1], al[im], bh[ib].y, bh[ib].w);
                }
        }
        asm volatile("cp.async.wait_group 1;" ::: "memory");
        __syncthreads();
    }

    // epilogue
    const int g  = lane >> 2;
    const int t2 = (lane & 3) << 1;
    #pragma unroll
    for (int im = 0; im < 2; im++) {
        const int row0 = blockRow + wm + im * 16 + g;
        #pragma unroll
        for (int j = 0; j < 4; j++) {
            const int col = blockCol + wn + j * 8 + t2;
            float4 v = d[im][j];
            if (bias != nullptr) {
                float b0 = bias[col], b1 = bias[col + 1];
                v.x += b0; v.y += b1; v.z += b0; v.w += b1;
            }
            *(float2*)&C[(size_t)row0 * N + col]       = make_float2(v.x, v.y);
            *(float2*)&C[(size_t)(row0 + 8) * N + col] = make_float2(v.z, v.w);
        }
    }
}

// ---------------------------------------------------------------------------
// Sparse neighbor attention (verified). Writes output as bf16 hi/lo split.
// ---------------------------------------------------------------------------
__global__ __launch_bounds__(256) void attn_kernel(
    const int* __restrict__ idx, const float* __restrict__ bias)
{
    const int bq   = blockIdx.x;
    const int b    = bq >> 13;
    const int h    = threadIdx.x >> 5;
    const int lane = threadIdx.x & 31;

    __shared__ float qs[INNER_];
    #pragma unroll
    for (int i = threadIdx.x; i < INNER_; i += 256)
        qs[i] = g_q[(size_t)bq * INNER_ + i];
    __syncthreads();

    const int   row = b * L_ + (idx[(size_t)bq * KN_ + lane] & (L_ - 1));
    const float bj  = bias[(size_t)bq * KN_ + lane];

    const float* krow = g_kv + (size_t)row * (2 * INNER_) + h * DH_;
    float sim = 0.f;
    #pragma unroll
    for (int t = 0; t < DH_; t += 4) {
        float4 k4 = *(const float4*)(krow + t);
        sim = fmaf(qs[h * DH_ + t + 0], k4.x, sim);
        sim = fmaf(qs[h * DH_ + t + 1], k4.y, sim);
        sim = fmaf(qs[h * DH_ + t + 2], k4.z, sim);
        sim = fmaf(qs[h * DH_ + t + 3], k4.w, sim);
    }
    sim = sim * 0.125f + bj;

    float m = sim;
    #pragma unroll
    for (int o = 16; o; o >>= 1) m = fmaxf(m, __shfl_xor_sync(0xffffffffu, m, o));
    float e = __expf(sim - m);
    float s = e;
    #pragma unroll
    for (int o = 16; o; o >>= 1) s += __shfl_xor_sync(0xffffffffu, s, o);
    const float p = e / s;

    float2 acc = make_float2(0.f, 0.f);
    const int off = h * DH_ + lane * 2;
    #pragma unroll
    for (int j = 0; j < KN_; j++) {
        const int   rj = __shfl_sync(0xffffffffu, row, j);
        const float pj = __shfl_sync(0xffffffffu, p, j);
        const float2 v2 = *(const float2*)(g_kv + (size_t)rj * (2 * INNER_) + INNER_ + off);
        acc.x = fmaf(pj, v2.x, acc.x);
        acc.y = fmaf(pj, v2.y, acc.y);
    }
    unsigned whi, wlo;
    split_pack(acc.x, acc.y, whi, wlo);
    const size_t widx = ((size_t)bq * INNER_ + off) >> 1;
    ((unsigned*)g_at_hi)[widx] = whi;
    ((unsigned*)g_at_lo)[widx] = wlo;
}

// ---------------------------------------------------------------------------
extern "C" void kernel_launch(void* const* d_in, const int* in_sizes, int n_in,
                              void* d_out, int out_size)
{
    const float* x       = (const float*)d_in[0];
    const float* context = (const float*)d_in[1];
    const int*   idx     = (const int*)d_in[2];
    const float* bias    = (const float*)d_in[3];
    const float* Wq      = (const float*)d_in[4];
    const float* Wkv     = (const float*)d_in[5];
    const float* Wo      = (const float*)d_in[6];
    const float* bo      = (const float*)d_in[7];
    float*       out     = (float*)d_out;

    float *pq, *pkv;
    __nv_bfloat16 *xh, *xl, *ch, *cl, *qh, *ql, *kh, *kl, *oh, *ol, *ath, *atl;
    cudaGetSymbolAddress((void**)&pq,  g_q);
    cudaGetSymbolAddress((void**)&pkv, g_kv);
    cudaGetSymbolAddress((void**)&xh,  g_x_hi);   cudaGetSymbolAddress((void**)&xl,  g_x_lo);
    cudaGetSymbolAddress((void**)&ch,  g_c_hi);   cudaGetSymbolAddress((void**)&cl,  g_c_lo);
    cudaGetSymbolAddress((void**)&qh,  g_wq_hi);  cudaGetSymbolAddress((void**)&ql,  g_wq_lo);
    cudaGetSymbolAddress((void**)&kh,  g_wkv_hi); cudaGetSymbolAddress((void**)&kl,  g_wkv_lo);
    cudaGetSymbolAddress((void**)&oh,  g_wo_hi);  cudaGetSymbolAddress((void**)&ol,  g_wo_lo);
    cudaGetSymbolAddress((void**)&ath, g_at_hi);  cudaGetSymbolAddress((void**)&atl, g_at_lo);

    cudaFuncSetAttribute(gemm_bf16s,
        cudaFuncAttributeMaxDynamicSharedMemorySize, SMEM_BYTES);

    // split inputs to bf16 hi/lo
    auto splt = [&](const float* s, __nv_bfloat16* h, __nv_bfloat16* l, int n) {
        split_kernel<<<(n / 4 + 255) / 256, 256>>>(
            (const float4*)s, (uint2*)h, (uint2*)l, n / 4);
    };
    splt(x,       xh, xl, MQ * D_);
    splt(context, ch, cl, MC * D_);
    splt(Wq,      qh, ql, D_ * INNER_);
    splt(Wkv,     kh, kl, D_ * 2 * INNER_);
    splt(Wo,      oh, ol, INNER_ * D_);

    // q = x @ Wq
    gemm_bf16s<<<dim3(INNER_ / 128, MQ / 128), 512, SMEM_BYTES>>>(
        xh, xl, qh, ql, pq, MQ, INNER_, D_, nullptr);
    // kv = context @ Wkv
    gemm_bf16s<<<dim3((2 * INNER_) / 128, MC / 128), 512, SMEM_BYTES>>>(
        ch, cl, kh, kl, pkv, MC, 2 * INNER_, D_, nullptr);
    // sparse attention -> split bf16 attn matrix
    attn_kernel<<<MQ, 256>>>(idx, bias);
    // out = attn @ Wo + bo
    gemm_bf16s<<<dim3(D_ / 128, MQ / 128), 512, SMEM_BYTES>>>(
        ath, atl, oh, ol, out, MQ, D_, INNER_, bo);
}

// round 7
// speedup vs baseline: 1.2575x; 1.2575x over previous
#include <cuda_runtime.h>
#include <cuda_bf16.h>
#include <cuda_fp16.h>

#define B_ 2
#define HW_ 8192
#define D_ 512
#define L_ 4096
#define KN_ 32
#define HEADS_ 8
#define DH_ 64
#define INNER_ 512
#define MQ (B_ * HW_)   /* 16384 */
#define MC (B_ * L_)    /* 8192  */

// ---------------- device-global scratch (no cudaMalloc allowed) -------------
__device__ float  g_q[MQ * INNER_];            // fp32 q (attn consumes fp32)
__device__ __half g_kv16[MC * 2 * INNER_];     // fp16 kv (attn gathers, half traffic)
__device__ __nv_bfloat16 g_x_hi[MQ * D_],           g_x_lo[MQ * D_];
__device__ __nv_bfloat16 g_c_hi[MC * D_],           g_c_lo[MC * D_];
__device__ __nv_bfloat16 g_wq_hi[D_ * INNER_],      g_wq_lo[D_ * INNER_];
__device__ __nv_bfloat16 g_wkv_hi[D_ * 2 * INNER_], g_wkv_lo[D_ * 2 * INNER_];
__device__ __nv_bfloat16 g_wo_hi[INNER_ * D_],      g_wo_lo[INNER_ * D_];
__device__ __nv_bfloat16 g_at_hi[MQ * INNER_],      g_at_lo[MQ * INNER_];

// ---------------- helpers ----------------------------------------------------
__device__ __forceinline__ void split_pack(float a, float b,
                                           unsigned &whi, unsigned &wlo) {
    __nv_bfloat16 ah = __float2bfloat16(a);
    __nv_bfloat16 bh = __float2bfloat16(b);
    __nv_bfloat16 al = __float2bfloat16(a - __bfloat162float(ah));
    __nv_bfloat16 bl = __float2bfloat16(b - __bfloat162float(bh));
    unsigned short ahu = *(unsigned short*)&ah, bhu = *(unsigned short*)&bh;
    unsigned short alu = *(unsigned short*)&al, blu = *(unsigned short*)&bl;
    whi = ((unsigned)bhu << 16) | ahu;
    wlo = ((unsigned)blu << 16) | alu;
}
__device__ __forceinline__ void ldsm_x4(uint4 &r, unsigned addr) {
    asm volatile("ldmatrix.sync.aligned.m8n8.x4.shared.b16 {%0,%1,%2,%3}, [%4];"
        : "=r"(r.x), "=r"(r.y), "=r"(r.z), "=r"(r.w) : "r"(addr));
}
__device__ __forceinline__ void ldsm_x4_t(uint4 &r, unsigned addr) {
    asm volatile("ldmatrix.sync.aligned.m8n8.x4.trans.shared.b16 {%0,%1,%2,%3}, [%4];"
        : "=r"(r.x), "=r"(r.y), "=r"(r.z), "=r"(r.w) : "r"(addr));
}
__device__ __forceinline__ void mma_bf16(float4 &d, const uint4 &a,
                                         unsigned b0, unsigned b1) {
    asm volatile("mma.sync.aligned.m16n8k16.row.col.f32.bf16.bf16.f32 "
        "{%0,%1,%2,%3}, {%4,%5,%6,%7}, {%8,%9}, {%0,%1,%2,%3};"
        : "+f"(d.x), "+f"(d.y), "+f"(d.z), "+f"(d.w)
        : "r"(a.x), "r"(a.y), "r"(a.z), "r"(a.w), "r"(b0), "r"(b1));
}
__device__ __forceinline__ void cp16(unsigned saddr, const void* gaddr) {
    asm volatile("cp.async.cg.shared.global [%0], [%1], 16;"
        :: "r"(saddr), "l"(gaddr));
}

// ---------------- fp32 -> bf16 hi/lo split (memory-bound) -------------------
__global__ __launch_bounds__(256) void split_kernel(
    const float4* __restrict__ src, uint2* __restrict__ hi,
    uint2* __restrict__ lo, int n4)
{
    int i = blockIdx.x * 256 + threadIdx.x;
    if (i >= n4) return;
    float4 v = src[i];
    unsigned h0, l0, h1, l1;
    split_pack(v.x, v.y, h0, l0);
    split_pack(v.z, v.w, h1, l1);
    hi[i] = make_uint2(h0, h1);
    lo[i] = make_uint2(l0, l1);
}

// ---------------------------------------------------------------------------
// Tensor-core GEMM, bf16 hi/lo split inputs. C = A[M,K] @ B[K,N] (+bias).
// Block tile 128x64xK32, 256 threads = 8 warps (4x2 grid of the verified
// 32x32 warp tile). __launch_bounds__(256,2) -> 2 CTAs/SM so barrier /
// cp.async stalls of one block are filled by the other (R3-R5 were
// concurrency-starved: 1 CTA/SM, nothing saturated).
// A smem [m][k] stride 20 words; B smem [k][n] stride 36 words (rows hit
// banks 0,4,..28 x4 -> conflict-free ldmatrix.trans).
// out_half: write C as fp16 (kv path) instead of fp32.
// ---------------------------------------------------------------------------
#define AW 20
#define BW2 36
#define A_LO_OFF 10240          /* 128*20 words * 4B */
#define B_HI_OFF 20480
#define B_LO_OFF 25088          /* +32*36*4 */
#define STG_BYTES 29696         /* 2*10240 + 2*4608 */
#define SMEM_BYTES (3 * STG_BYTES)

__global__ __launch_bounds__(256, 2) void gemm_bf16s(
    const __nv_bfloat16* __restrict__ Ah, const __nv_bfloat16* __restrict__ Al,
    const __nv_bfloat16* __restrict__ Bh, const __nv_bfloat16* __restrict__ Bl,
    void* __restrict__ Cv, int M, int N, int K, const float* __restrict__ bias,
    int out_half)
{
    extern __shared__ unsigned sm[];
    const unsigned smbase = (unsigned)__cvta_generic_to_shared(sm);

    const int tid  = threadIdx.x;
    const int lane = tid & 31;
    const int warp = tid >> 5;
    const int wm   = (warp >> 1) * 32;   // 4 warps down M (128)
    const int wn   = (warp & 1) * 32;    // 2 warps across N (64)
    const int blockRow = blockIdx.y * 128;
    const int blockCol = blockIdx.x * 64;

    // cp.async loader map: A 128 rows x 4 chunks (2 per thread), B 32 x 8
    const int ar = tid >> 1, ac = (tid & 1) * 2;   // chunk pair
    const int bk = tid >> 3, bc = tid & 7;
    const __nv_bfloat16* gAh = Ah + (size_t)(blockRow + ar) * K + ac * 8;
    const __nv_bfloat16* gAl = Al + (size_t)(blockRow + ar) * K + ac * 8;
    const __nv_bfloat16* gBh = Bh + (size_t)bk * N + blockCol + bc * 8;
    const __nv_bfloat16* gBl = Bl + (size_t)bk * N + blockCol + bc * 8;
    const unsigned a_sb = ar * 80 + ac * 16;
    const unsigned b_sb = bk * 144 + bc * 16;

    // ldmatrix lane maps (verified layout, word offsets)
    const int a_l_row = lane & 15;
    const int a_l_k   = (lane >> 4) << 2;
    const int b_l_k   = (lane & 7) + ((lane >> 4) << 3);
    const int b_l_n   = ((lane >> 3) & 1) << 2;

    float4 d[2][4];
    #pragma unroll
    for (int i = 0; i < 2; i++)
        #pragma unroll
        for (int j = 0; j < 4; j++) d[i][j] = make_float4(0.f, 0.f, 0.f, 0.f);

    auto issue = [&](int stage, int k0) {
        unsigned s = smbase + stage * STG_BYTES;
        cp16(s + a_sb,                 gAh + k0);
        cp16(s + a_sb + 16,            gAh + k0 + 8);
        cp16(s + A_LO_OFF + a_sb,      gAl + k0);
        cp16(s + A_LO_OFF + a_sb + 16, gAl + k0 + 8);
        cp16(s + B_HI_OFF + b_sb,      gBh + (size_t)k0 * N);
        cp16(s + B_LO_OFF + b_sb,      gBl + (size_t)k0 * N);
    };

    issue(0, 0);
    asm volatile("cp.async.commit_group;" ::: "memory");
    issue(1, 32);
    asm volatile("cp.async.commit_group;" ::: "memory");
    asm volatile("cp.async.wait_group 1;" ::: "memory");
    __syncthreads();

    const int nK = K >> 5;
    for (int i = 0; i < nK; i++) {
        const int stage = i % 3;
        const int kn = (i + 2) << 5;
        if (kn < K) issue((i + 2) % 3, kn);
        asm volatile("cp.async.commit_group;" ::: "memory");

        const unsigned sb = smbase + stage * STG_BYTES;
        #pragma unroll
        for (int kk = 0; kk < 2; kk++) {
            uint4 ah[2], al[2], bh[2], bl[2];
            #pragma unroll
            for (int im = 0; im < 2; im++) {
                unsigned w = ((wm + im * 16 + a_l_row) * AW + kk * 8 + a_l_k) * 4;
                ldsm_x4(ah[im], sb + w);
                ldsm_x4(al[im], sb + A_LO_OFF + w);
            }
            #pragma unroll
            for (int ib = 0; ib < 2; ib++) {
                unsigned w = ((kk * 16 + b_l_k) * BW2 + ((wn + ib * 16) >> 1) + b_l_n) * 4;
                ldsm_x4_t(bh[ib], sb + B_HI_OFF + w);
                ldsm_x4_t(bl[ib], sb + B_LO_OFF + w);
            }
            #pragma unroll
            for (int im = 0; im < 2; im++)
                #pragma unroll
                for (int ib = 0; ib < 2; ib++) {
                    mma_bf16(d[im][ib * 2 + 0], ah[im], bh[ib].x, bh[ib].z);
                    mma_bf16(d[im][ib * 2 + 1], ah[im], bh[ib].y, bh[ib].w);
                }
            #pragma unroll
            for (int im = 0; im < 2; im++)
                #pragma unroll
                for (int ib = 0; ib < 2; ib++) {
                    mma_bf16(d[im][ib * 2 + 0], ah[im], bl[ib].x, bl[ib].z);
                    mma_bf16(d[im][ib * 2 + 1], ah[im], bl[ib].y, bl[ib].w);
                }
            #pragma unroll
            for (int im = 0; im < 2; im++)
                #pragma unroll
                for (int ib = 0; ib < 2; ib++) {
                    mma_bf16(d[im][ib * 2 + 0], al[im], bh[ib].x, bh[ib].z);
                    mma_bf16(d[im][ib * 2 + 1], al[im], bh[ib].y, bh[ib].w);
                }
        }
        asm volatile("cp.async.wait_group 1;" ::: "memory");
        __syncthreads();
    }

    // epilogue
    const int g  = lane >> 2;
    const int t2 = (lane & 3) << 1;
    #pragma unroll
    for (int im = 0; im < 2; im++) {
        const int row0 = blockRow + wm + im * 16 + g;
        #pragma unroll
        for (int j = 0; j < 4; j++) {
            const int col = blockCol + wn + j * 8 + t2;
            float4 v = d[im][j];
            if (bias != nullptr) {
                float b0 = bias[col], b1 = bias[col + 1];
                v.x += b0; v.y += b1; v.z += b0; v.w += b1;
            }
            if (!out_half) {
                float* C = (float*)Cv;
                *(float2*)&C[(size_t)row0 * N + col]       = make_float2(v.x, v.y);
                *(float2*)&C[(size_t)(row0 + 8) * N + col] = make_float2(v.z, v.w);
            } else {
                __half* C = (__half*)Cv;
                *(__half2*)&C[(size_t)row0 * N + col]       = __floats2half2_rn(v.x, v.y);
                *(__half2*)&C[(size_t)(row0 + 8) * N + col] = __floats2half2_rn(v.z, v.w);
            }
        }
    }
}

// ---------------------------------------------------------------------------
// Sparse neighbor attention, fp16 KV gather (half the L2 traffic).
// One block per query; warp h = head h; lane j = neighbor j for QK,
// lane l = output dims (2l,2l+1) for PV. fp32 accumulation throughout.
// ---------------------------------------------------------------------------
__global__ __launch_bounds__(256) void attn_kernel(
    const int* __restrict__ idx, const float* __restrict__ bias)
{
    const int bq   = blockIdx.x;
    const int b    = bq >> 13;
    const int h    = threadIdx.x >> 5;
    const int lane = threadIdx.x & 31;

    __shared__ float qs[INNER_];
    #pragma unroll
    for (int i = threadIdx.x; i < INNER_; i += 256)
        qs[i] = g_q[(size_t)bq * INNER_ + i];
    __syncthreads();

    const int   row = b * L_ + (idx[(size_t)bq * KN_ + lane] & (L_ - 1));
    const float bj  = bias[(size_t)bq * KN_ + lane];

    const uint4* kp = (const uint4*)(g_kv16 + (size_t)row * (2 * INNER_) + h * DH_);
    float sim = 0.f;
    #pragma unroll
    for (int t = 0; t < 8; t++) {           // 8 x 16B = 64 halves
        uint4 u = kp[t];
        float2 f0 = __half22float2(*(__half2*)&u.x);
        float2 f1 = __half22float2(*(__half2*)&u.y);
        float2 f2 = __half22float2(*(__half2*)&u.z);
        float2 f3 = __half22float2(*(__half2*)&u.w);
        const float* q8 = qs + h * DH_ + t * 8;
        sim = fmaf(q8[0], f0.x, sim); sim = fmaf(q8[1], f0.y, sim);
        sim = fmaf(q8[2], f1.x, sim); sim = fmaf(q8[3], f1.y, sim);
        sim = fmaf(q8[4], f2.x, sim); sim = fmaf(q8[5], f2.y, sim);
        sim = fmaf(q8[6], f3.x, sim); sim = fmaf(q8[7], f3.y, sim);
    }
    sim = sim * 0.125f + bj;

    float m = sim;
    #pragma unroll
    for (int o = 16; o; o >>= 1) m = fmaxf(m, __shfl_xor_sync(0xffffffffu, m, o));
    float e = __expf(sim - m);
    float s = e;
    #pragma unroll
    for (int o = 16; o; o >>= 1) s += __shfl_xor_sync(0xffffffffu, s, o);
    const float p = e / s;

    float2 acc = make_float2(0.f, 0.f);
    const int off = h * DH_ + lane * 2;
    #pragma unroll
    for (int j = 0; j < KN_; j++) {
        const int   rj = __shfl_sync(0xffffffffu, row, j);
        const float pj = __shfl_sync(0xffffffffu, p, j);
        float2 v2 = __half22float2(
            *(const __half2*)(g_kv16 + (size_t)rj * (2 * INNER_) + INNER_ + off));
        acc.x = fmaf(pj, v2.x, acc.x);
        acc.y = fmaf(pj, v2.y, acc.y);
    }
    unsigned whi, wlo;
    split_pack(acc.x, acc.y, whi, wlo);
    const size_t widx = ((size_t)bq * INNER_ + off) >> 1;
    ((unsigned*)g_at_hi)[widx] = whi;
    ((unsigned*)g_at_lo)[widx] = wlo;
}

// ---------------------------------------------------------------------------
extern "C" void kernel_launch(void* const* d_in, const int* in_sizes, int n_in,
                              void* d_out, int out_size)
{
    const float* x       = (const float*)d_in[0];
    const float* context = (const float*)d_in[1];
    const int*   idx     = (const int*)d_in[2];
    const float* bias    = (const float*)d_in[3];
    const float* Wq      = (const float*)d_in[4];
    const float* Wkv     = (const float*)d_in[5];
    const float* Wo      = (const float*)d_in[6];
    const float* bo      = (const float*)d_in[7];
    float*       out     = (float*)d_out;

    float *pq; __half *pkv16;
    __nv_bfloat16 *xh, *xl, *ch, *cl, *qh, *ql, *kh, *kl, *oh, *ol, *ath, *atl;
    cudaGetSymbolAddress((void**)&pq,    g_q);
    cudaGetSymbolAddress((void**)&pkv16, g_kv16);
    cudaGetSymbolAddress((void**)&xh,  g_x_hi);   cudaGetSymbolAddress((void**)&xl,  g_x_lo);
    cudaGetSymbolAddress((void**)&ch,  g_c_hi);   cudaGetSymbolAddress((void**)&cl,  g_c_lo);
    cudaGetSymbolAddress((void**)&qh,  g_wq_hi);  cudaGetSymbolAddress((void**)&ql,  g_wq_lo);
    cudaGetSymbolAddress((void**)&kh,  g_wkv_hi); cudaGetSymbolAddress((void**)&kl,  g_wkv_lo);
    cudaGetSymbolAddress((void**)&oh,  g_wo_hi);  cudaGetSymbolAddress((void**)&ol,  g_wo_lo);
    cudaGetSymbolAddress((void**)&ath, g_at_hi);  cudaGetSymbolAddress((void**)&atl, g_at_lo);

    cudaFuncSetAttribute(gemm_bf16s,
        cudaFuncAttributeMaxDynamicSharedMemorySize, SMEM_BYTES);

    auto splt = [&](const float* s, __nv_bfloat16* h, __nv_bfloat16* l, int n) {
        split_kernel<<<(n / 4 + 255) / 256, 256>>>(
            (const float4*)s, (uint2*)h, (uint2*)l, n / 4);
    };
    splt(x,       xh, xl, MQ * D_);
    splt(context, ch, cl, MC * D_);
    splt(Wq,      qh, ql, D_ * INNER_);
    splt(Wkv,     kh, kl, D_ * 2 * INNER_);
    splt(Wo,      oh, ol, INNER_ * D_);

    // q = x @ Wq (fp32 out)
    gemm_bf16s<<<dim3(INNER_ / 64, MQ / 128), 256, SMEM_BYTES>>>(
        xh, xl, qh, ql, pq, MQ, INNER_, D_, nullptr, 0);
    // kv = context @ Wkv (fp16 out for attention gather)
    gemm_bf16s<<<dim3((2 * INNER_) / 64, MC / 128), 256, SMEM_BYTES>>>(
        ch, cl, kh, kl, pkv16, MC, 2 * INNER_, D_, nullptr, 1);
    // sparse attention -> split bf16 attn matrix
    attn_kernel<<<MQ, 256>>>(idx, bias);
    // out = attn @ Wo + bo (fp32 out)
    gemm_bf16s<<<dim3(D_ / 64, MQ / 128), 256, SMEM_BYTES>>>(
        ath, atl, oh, ol, out, MQ, D_, INNER_, bo, 0);
}